// round 5
// baseline (speedup 1.0000x reference)
#include <cuda_runtime.h>
#include <math.h>
#include <cstdint>

#define NN    50000
#define NPAD  50048          // 782 * 64 = 391 * 128
#define EE    800000

// ---------------- scratch (device globals; no allocation) ----------------
__device__ float g_AGGX[(size_t)NPAD * 256];   // aggregated [x | perb]
__device__ float g_AGG[(size_t)NPAD * 512];    // [on_x | on_p | tg_x | tg_p]
__device__ float g_P1[(size_t)NPAD * 256];     // [h1x | h1y]
__device__ int   g_deg[NN];
__device__ int   g_off[NN + 8];
__device__ int   g_cur[NN];
__device__ int   g_btot[64];
__device__ int   g_scol[EE];
__device__ float g_sw[EE];
__device__ float g_bnsum[512];                 // [sum(256) | sumsq(256)]
__device__ float g_bnaff[512];                 // [scale(256) | shift(256)]
__device__ float g_c1[128];                    // b_on @ W1 + b1
__device__ float g_loss;

// ---------------- packed f32x2 helpers ----------------
__device__ __forceinline__ unsigned long long dup2(float a) {
    unsigned long long d;
    unsigned int u = __float_as_uint(a);
    asm("mov.b64 %0, {%1, %1};" : "=l"(d) : "r"(u));
    return d;
}
__device__ __forceinline__ void fma2(unsigned long long& acc, unsigned long long a,
                                     unsigned long long b) {
    asm("fma.rn.f32x2 %0, %1, %2, %0;" : "+l"(acc) : "l"(a), "l"(b));
}
__device__ __forceinline__ float2 unpack2(unsigned long long v) {
    unsigned int lo, hi;
    asm("mov.b64 {%0, %1}, %2;" : "=r"(lo), "=r"(hi) : "l"(v));
    return make_float2(__uint_as_float(lo), __uint_as_float(hi));
}

// ---------------- init ----------------
__global__ void k_zero() {
    int i = blockIdx.x * 256 + threadIdx.x;
    if (i < NN)  g_deg[i] = 0;
    if (i < 512) g_bnsum[i] = 0.f;
    if (i == 0)  g_loss = 0.f;
}
__global__ void k_hist(const int* __restrict__ row) {
    int e = blockIdx.x * 256 + threadIdx.x;
    if (e < EE) atomicAdd(&g_deg[row[e]], 1);
}

// ---------------- 3-pass scan ----------------
__global__ __launch_bounds__(1024) void k_scan1() {
    __shared__ int wsum[32];
    int t = threadIdx.x, lane = t & 31, wid = t >> 5;
    int idx = blockIdx.x * 1024 + t;
    int v = (idx < NN) ? g_deg[idx] : 0;
    int incl = v;
    #pragma unroll
    for (int s = 1; s < 32; s <<= 1) {
        int a = __shfl_up_sync(0xFFFFFFFFu, incl, s);
        if (lane >= s) incl += a;
    }
    if (lane == 31) wsum[wid] = incl;
    __syncthreads();
    if (wid == 0) {
        int wv = wsum[lane];
        #pragma unroll
        for (int s = 1; s < 32; s <<= 1) {
            int a = __shfl_up_sync(0xFFFFFFFFu, wv, s);
            if (lane >= s) wv += a;
        }
        wsum[lane] = wv;
    }
    __syncthreads();
    int excl = (wid > 0 ? wsum[wid - 1] : 0) + incl - v;
    if (idx < NN) g_off[idx] = excl;
    if (t == 0) g_btot[blockIdx.x] = wsum[31];
}
__global__ void k_scan2() {
    if (threadIdx.x == 0) {
        int run = 0;
        for (int i = 0; i < 49; i++) { int v = g_btot[i]; g_btot[i] = run; run += v; }
        g_off[NN] = run;
    }
}
__global__ __launch_bounds__(1024) void k_scan3() {
    int idx = blockIdx.x * 1024 + threadIdx.x;
    if (idx < NN) {
        int o = g_off[idx] + g_btot[blockIdx.x];
        g_off[idx] = o;
        g_cur[idx] = o;
    }
}
__global__ void k_scatter(const int* __restrict__ row, const int* __restrict__ col,
                          const float* __restrict__ w) {
    int e = blockIdx.x * 256 + threadIdx.x;
    if (e < EE) {
        int r = row[e];
        int p = atomicAdd(&g_cur[r], 1);
        g_scol[p] = col[e];
        g_sw[p]   = w[e];
    }
}

// ---------------- sparse aggregation of raw [x | perb] ----------------
__global__ __launch_bounds__(128) void k_aggregate(const float* __restrict__ x,
                                                   const float* __restrict__ perb) {
    int t = threadIdx.x, lane = t & 31, wid = t >> 5;
    int r = blockIdx.x * 2 + (wid >> 1);
    int part = wid & 1;
    const float4* src = part ? (const float4*)perb : (const float4*)x;
    int s = g_off[r], e = g_off[r + 1];
    float ax = 0.f, ay = 0.f, az = 0.f, aw = 0.f;
    int i = s;
    for (; i + 4 <= e; i += 4) {
        int c0 = g_scol[i], c1 = g_scol[i + 1], c2 = g_scol[i + 2], c3 = g_scol[i + 3];
        float w0 = g_sw[i], w1 = g_sw[i + 1], w2 = g_sw[i + 2], w3 = g_sw[i + 3];
        float4 h0 = src[(size_t)c0 * 32 + lane];
        float4 h1 = src[(size_t)c1 * 32 + lane];
        float4 h2 = src[(size_t)c2 * 32 + lane];
        float4 h3 = src[(size_t)c3 * 32 + lane];
        ax += w0 * h0.x + w1 * h1.x + w2 * h2.x + w3 * h3.x;
        ay += w0 * h0.y + w1 * h1.y + w2 * h2.y + w3 * h3.y;
        az += w0 * h0.z + w1 * h1.z + w2 * h2.z + w3 * h3.z;
        aw += w0 * h0.w + w1 * h1.w + w2 * h2.w + w3 * h3.w;
    }
    for (; i < e; i++) {
        int c = g_scol[i]; float w = g_sw[i];
        float4 h = src[(size_t)c * 32 + lane];
        ax += w * h.x; ay += w * h.y; az += w * h.z; aw += w * h.w;
    }
    ((float4*)g_AGGX)[(size_t)r * 64 + part * 32 + lane] = make_float4(ax, ay, az, aw);
}

// ---------------- f32x2 GEMM core ----------------
// sA: 64x128 fp32 row-major (LD 128), sB: 128x128 fp32 row-major (LD 128)
// 128 threads: ty=t>>4 owns rows ty*8..+7, tx=t&15 owns cols tx*8..+7 (4 f32-pairs)
#define SM_B 8192                       // float offset of B in dynamic smem
#define DYN_SMEM ((8192 + 16384) * 4)   // 96 KB

__device__ __forceinline__ void mm64(const float* __restrict__ sA,
                                     const float* __restrict__ sB,
                                     int t, unsigned long long acc[8][4]) {
    int ty = t >> 4, tx = t & 15;
    const float* Ab = sA + ty * 8 * 128;
    const ulonglong2* Bb = (const ulonglong2*)sB + tx * 2;
    #pragma unroll
    for (int r = 0; r < 8; r++)
        #pragma unroll
        for (int j = 0; j < 4; j++) acc[r][j] = 0ull;
    #pragma unroll 2
    for (int k = 0; k < 128; k++) {
        ulonglong2 b01 = Bb[k * 32];
        ulonglong2 b23 = Bb[k * 32 + 1];
        #pragma unroll
        for (int r = 0; r < 8; r++) {
            unsigned long long ad = dup2(Ab[r * 128 + k]);
            fma2(acc[r][0], ad, b01.x);
            fma2(acc[r][1], ad, b01.y);
            fma2(acc[r][2], ad, b23.x);
            fma2(acc[r][3], ad, b23.y);
        }
    }
}
__device__ __forceinline__ void stage_B(float* sB, const float* __restrict__ W, int t) {
    float4* d = (float4*)sB;
    const float4* s = (const float4*)W;
    #pragma unroll
    for (int i = 0; i < 32; i++) d[t + i * 128] = s[t + i * 128];
}

// ---------------- c1 = b_on @ W1 + b1 ----------------
__global__ void k_c1(const float* __restrict__ b_on, const float* __restrict__ W1,
                     const float* __restrict__ b1) {
    int n = threadIdx.x;
    float s = b1[n];
    for (int k = 0; k < 128; k++) s += b_on[k] * W1[k * 128 + n];
    g_c1[n] = s;
}

// ---------------- feature GEMMs: AGG[:,sec*128:+128] = AGGX_part @ W ----------------
__global__ __launch_bounds__(128, 2) void k_mm_feat(const float* __restrict__ W_on,
                                                    const float* __restrict__ W_tg) {
    extern __shared__ float sm[];
    float* sA = sm; float* sB = sm + SM_B;
    int t = threadIdx.x;
    int sec = blockIdx.y, row0 = blockIdx.x * 64;
    stage_B(sB, (sec < 2) ? W_on : W_tg, t);
    const float4* A4 = (const float4*)(g_AGGX + (sec & 1) * 128);
    #pragma unroll
    for (int i = 0; i < 16; i++) {
        int idx = t + i * 128;
        int r = idx >> 5, c4 = idx & 31;
        int gr = row0 + r;
        float4 v = make_float4(0.f, 0.f, 0.f, 0.f);
        if (gr < NN) v = A4[(size_t)gr * 64 + c4];
        ((float4*)sA)[idx] = v;
    }
    __syncthreads();
    unsigned long long acc[8][4];
    mm64(sA, sB, t, acc);
    int ty = t >> 4, tx = t & 15;
    float* Out = g_AGG + ((size_t)row0 + ty * 8) * 512 + sec * 128 + tx * 8;
    #pragma unroll
    for (int r = 0; r < 8; r++) {
        float2 v0 = unpack2(acc[r][0]), v1 = unpack2(acc[r][1]);
        float2 v2 = unpack2(acc[r][2]), v3 = unpack2(acc[r][3]);
        *(float4*)(Out + (size_t)r * 512)     = make_float4(v0.x, v0.y, v1.x, v1.y);
        *(float4*)(Out + (size_t)r * 512 + 4) = make_float4(v2.x, v2.y, v3.x, v3.y);
    }
}

// ---------------- embed = x + perb + agg_on_x + agg_on_p + b_on ----------------
__global__ void k_embed(const float* __restrict__ x, const float* __restrict__ perb,
                        const float* __restrict__ b_on, float* __restrict__ out) {
    int id = blockIdx.x * 256 + threadIdx.x;  // float4 index
    if (id < NN * 32) {
        int r = id >> 5, c = id & 31;
        float4 xv = ((const float4*)x)[id];
        float4 pv = ((const float4*)perb)[id];
        float4 a0 = ((const float4*)g_AGG)[(size_t)r * 128 + c];
        float4 a1 = ((const float4*)g_AGG)[(size_t)r * 128 + 32 + c];
        float4 bv = ((const float4*)b_on)[c];
        ((float4*)out)[id] = make_float4(xv.x + pv.x + a0.x + a1.x + bv.x,
                                         xv.y + pv.y + a0.y + a1.y + bv.y,
                                         xv.z + pv.z + a0.z + a1.z + bv.z,
                                         xv.w + pv.w + a0.w + a1.w + bv.w);
    }
}

// ---------------- pred stage 1: P1 = online @ W1 + c1 ; fused BN stats ----------------
__global__ __launch_bounds__(128, 2) void k_mm_p1(const float* __restrict__ W1) {
    extern __shared__ float sm[];
    float* sA = sm; float* sB = sm + SM_B;
    int t = threadIdx.x;
    int sec = blockIdx.y, row0 = blockIdx.x * 64;
    stage_B(sB, W1, t);
    const float4* A4 = (const float4*)g_AGG;
    #pragma unroll
    for (int i = 0; i < 16; i++) {
        int idx = t + i * 128;
        int r = idx >> 5, c4 = idx & 31;
        int gr = row0 + r;
        float4 v = make_float4(0.f, 0.f, 0.f, 0.f);
        if (gr < NN) {
            v = A4[(size_t)gr * 128 + c4];
            if (sec) {
                float4 u = A4[(size_t)gr * 128 + 32 + c4];
                v.x += u.x; v.y += u.y; v.z += u.z; v.w += u.w;
            }
        }
        ((float4*)sA)[idx] = v;
    }
    __syncthreads();
    unsigned long long acc[8][4];
    mm64(sA, sB, t, acc);
    int ty = t >> 4, tx = t & 15;
    float4 c1a = *(const float4*)(g_c1 + tx * 8);
    float4 c1b = *(const float4*)(g_c1 + tx * 8 + 4);
    float* Out = g_P1 + ((size_t)row0 + ty * 8) * 256 + sec * 128 + tx * 8;
    float ps[8] = {0.f,0.f,0.f,0.f,0.f,0.f,0.f,0.f};
    float qs[8] = {0.f,0.f,0.f,0.f,0.f,0.f,0.f,0.f};
    #pragma unroll
    for (int r = 0; r < 8; r++) {
        float2 v0 = unpack2(acc[r][0]), v1 = unpack2(acc[r][1]);
        float2 v2 = unpack2(acc[r][2]), v3 = unpack2(acc[r][3]);
        float4 o0 = make_float4(v0.x + c1a.x, v0.y + c1a.y, v1.x + c1a.z, v1.y + c1a.w);
        float4 o1 = make_float4(v2.x + c1b.x, v2.y + c1b.y, v3.x + c1b.z, v3.y + c1b.w);
        *(float4*)(Out + (size_t)r * 256)     = o0;
        *(float4*)(Out + (size_t)r * 256 + 4) = o1;
        if (row0 + ty * 8 + r < NN) {
            ps[0]+=o0.x; ps[1]+=o0.y; ps[2]+=o0.z; ps[3]+=o0.w;
            ps[4]+=o1.x; ps[5]+=o1.y; ps[6]+=o1.z; ps[7]+=o1.w;
            qs[0]+=o0.x*o0.x; qs[1]+=o0.y*o0.y; qs[2]+=o0.z*o0.z; qs[3]+=o0.w*o0.w;
            qs[4]+=o1.x*o1.x; qs[5]+=o1.y*o1.y; qs[6]+=o1.z*o1.z; qs[7]+=o1.w*o1.w;
        }
    }
    #pragma unroll
    for (int j = 0; j < 8; j++) {
        atomicAdd(&g_bnsum[sec * 128 + tx * 8 + j], ps[j]);
        atomicAdd(&g_bnsum[256 + sec * 128 + tx * 8 + j], qs[j]);
    }
}

__global__ void k_bn_final(const float* __restrict__ bn_g, const float* __restrict__ bn_b) {
    int t = threadIdx.x;  // 0..255
    float inv_n = 1.f / (float)NN;
    float mean = g_bnsum[t] * inv_n;
    float var = g_bnsum[256 + t] * inv_n - mean * mean;
    int f = t & 127;
    float sc = bn_g[f] * rsqrtf(var + 1e-5f);
    g_bnaff[t] = sc;
    g_bnaff[256 + t] = bn_b[f] - mean * sc;
}

// ---------------- pred stage 2 + cosine loss (P2 never leaves the block) ----------------
__global__ __launch_bounds__(128, 2) void k_mm_p2(const float* __restrict__ b_tg,
                                                  const float* __restrict__ prelu_a,
                                                  const float* __restrict__ W2,
                                                  const float* __restrict__ b2) {
    extern __shared__ float sm[];
    float* sA = sm; float* sB = sm + SM_B;
    int t = threadIdx.x;
    int sec = blockIdx.y, row0 = blockIdx.x * 64;
    float alpha = prelu_a[0];
    stage_B(sB, W2, t);
    #pragma unroll
    for (int i = 0; i < 16; i++) {
        int idx = t + i * 128;
        int r = idx >> 5, c4 = idx & 31;
        int gr = row0 + r;
        float4 v = make_float4(0.f, 0.f, 0.f, 0.f);
        if (gr < NN) {
            float4 h = *(const float4*)(g_P1 + (size_t)gr * 256 + sec * 128 + c4 * 4);
            float4 sc = *(const float4*)(g_bnaff + sec * 128 + c4 * 4);
            float4 sh = *(const float4*)(g_bnaff + 256 + sec * 128 + c4 * 4);
            v.x = h.x * sc.x + sh.x; v.x = v.x > 0.f ? v.x : alpha * v.x;
            v.y = h.y * sc.y + sh.y; v.y = v.y > 0.f ? v.y : alpha * v.y;
            v.z = h.z * sc.z + sh.z; v.z = v.z > 0.f ? v.z : alpha * v.z;
            v.w = h.w * sc.w + sh.w; v.w = v.w > 0.f ? v.w : alpha * v.w;
        }
        ((float4*)sA)[idx] = v;
    }
    __syncthreads();
    unsigned long long acc[8][4];
    mm64(sA, sB, t, acc);
    int ty = t >> 4, tx = t & 15;
    float4 bba = *(const float4*)(b2 + tx * 8);
    float4 bbb = *(const float4*)(b2 + tx * 8 + 4);
    float4 bta = *(const float4*)(b_tg + tx * 8);
    float4 btb = *(const float4*)(b_tg + tx * 8 + 4);
    float lsum = 0.f;
    #pragma unroll
    for (int r = 0; r < 8; r++) {
        int gr = row0 + ty * 8 + r;
        float dot = 0.f, np = 0.f, nt = 0.f;
        if (gr < NN) {
            float2 v0 = unpack2(acc[r][0]), v1 = unpack2(acc[r][1]);
            float2 v2 = unpack2(acc[r][2]), v3 = unpack2(acc[r][3]);
            float p0 = v0.x + bba.x, p1 = v0.y + bba.y, p2 = v1.x + bba.z, p3 = v1.y + bba.w;
            float p4 = v2.x + bbb.x, p5 = v2.y + bbb.y, p6 = v3.x + bbb.z, p7 = v3.y + bbb.w;
            float4 ta = *(const float4*)(g_AGG + (size_t)gr * 512 + 256 + tx * 8);
            float4 tb = *(const float4*)(g_AGG + (size_t)gr * 512 + 256 + tx * 8 + 4);
            if (sec == 0) {  // target_x = agg_tg_x + agg_tg_p + b_tg
                float4 ua = *(const float4*)(g_AGG + (size_t)gr * 512 + 384 + tx * 8);
                float4 ub = *(const float4*)(g_AGG + (size_t)gr * 512 + 384 + tx * 8 + 4);
                ta.x += ua.x; ta.y += ua.y; ta.z += ua.z; ta.w += ua.w;
                tb.x += ub.x; tb.y += ub.y; tb.z += ub.z; tb.w += ub.w;
            }
            ta.x += bta.x; ta.y += bta.y; ta.z += bta.z; ta.w += bta.w;
            tb.x += btb.x; tb.y += btb.y; tb.z += btb.z; tb.w += btb.w;
            dot = p0*ta.x + p1*ta.y + p2*ta.z + p3*ta.w + p4*tb.x + p5*tb.y + p6*tb.z + p7*tb.w;
            np  = p0*p0 + p1*p1 + p2*p2 + p3*p3 + p4*p4 + p5*p5 + p6*p6 + p7*p7;
            nt  = ta.x*ta.x + ta.y*ta.y + ta.z*ta.z + ta.w*ta.w
                + tb.x*tb.x + tb.y*tb.y + tb.z*tb.z + tb.w*tb.w;
        }
        // reduce across the 16 tx lanes (same ty) within the warp
        #pragma unroll
        for (int s = 8; s; s >>= 1) {
            dot += __shfl_xor_sync(0xFFFFFFFFu, dot, s);
            np  += __shfl_xor_sync(0xFFFFFFFFu, np, s);
            nt  += __shfl_xor_sync(0xFFFFFFFFu, nt, s);
        }
        if (tx == 0 && gr < NN) {
            float d1 = fmaxf(sqrtf(np), 1e-12f);
            float d2 = fmaxf(sqrtf(nt), 1e-12f);
            lsum += 2.f - 2.f * dot / (d1 * d2);
        }
    }
    if (tx == 0) atomicAdd(&g_loss, lsum);
}

__global__ void k_final(float* out, int out_size) {
    out[out_size - 1] = g_loss * (1.f / (float)NN);
}

// ---------------- host ----------------
extern "C" void kernel_launch(void* const* d_in, const int* in_sizes, int n_in,
                              void* d_out, int out_size) {
    const float* x       = (const float*)d_in[0];
    const float* perb    = (const float*)d_in[1];
    const int*   erow    = (const int*)d_in[2];
    const int*   ecol    = (const int*)d_in[3];
    const float* ew      = (const float*)d_in[4];
    const float* W_on    = (const float*)d_in[5];
    const float* b_on    = (const float*)d_in[6];
    const float* W_tg    = (const float*)d_in[7];
    const float* b_tg    = (const float*)d_in[8];
    const float* W1      = (const float*)d_in[9];
    const float* b1      = (const float*)d_in[10];
    const float* bn_g    = (const float*)d_in[11];
    const float* bn_b    = (const float*)d_in[12];
    const float* prelu_a = (const float*)d_in[13];
    const float* W2      = (const float*)d_in[14];
    const float* b2      = (const float*)d_in[15];
    float* out = (float*)d_out;

    cudaFuncSetAttribute(k_mm_feat, cudaFuncAttributeMaxDynamicSharedMemorySize, DYN_SMEM);
    cudaFuncSetAttribute(k_mm_p1,   cudaFuncAttributeMaxDynamicSharedMemorySize, DYN_SMEM);
    cudaFuncSetAttribute(k_mm_p2,   cudaFuncAttributeMaxDynamicSharedMemorySize, DYN_SMEM);

    k_zero<<<196, 256>>>();
    k_hist<<<3125, 256>>>(erow);
    k_c1<<<1, 128>>>(b_on, W1, b1);
    k_scan1<<<49, 1024>>>();
    k_scan2<<<1, 32>>>();
    k_scan3<<<49, 1024>>>();
    k_scatter<<<3125, 256>>>(erow, ecol, ew);
    k_aggregate<<<25000, 128>>>(x, perb);
    k_mm_feat<<<dim3(782, 4), 128, DYN_SMEM>>>(W_on, W_tg);
    k_embed<<<6250, 256>>>(x, perb, b_on, out);
    k_mm_p1<<<dim3(782, 2), 128, DYN_SMEM>>>(W1);
    k_bn_final<<<1, 256>>>(bn_g, bn_b);
    k_mm_p2<<<dim3(782, 2), 128, DYN_SMEM>>>(b_tg, prelu_a, W2, b2);
    k_final<<<1, 1>>>(out, out_size);
}

// round 7
// speedup vs baseline: 2.2475x; 2.2475x over previous
#include <cuda_runtime.h>
#include <cuda_bf16.h>
#include <mma.h>
#include <math.h>
#include <cstdint>

using namespace nvcuda;

#define NN    50000
#define NPAD  50048          // 391 * 128
#define EE    800000

// ---------------- scratch (device globals; no allocation) ----------------
__device__ float g_AGGX[(size_t)NPAD * 256];   // aggregated [x | perb]
__device__ float g_AGG[(size_t)NPAD * 512];    // [on_x | on_p | tg_x | tg_p]
__device__ float g_P1[(size_t)NPAD * 256];     // [h1x | h1y]
__device__ int   g_deg[NN];
__device__ int   g_off[NN + 8];
__device__ int   g_cur[NN];
__device__ int   g_btot[64];
__device__ int   g_scol[EE];
__device__ float g_sw[EE];
__device__ float g_bnsum[512];                 // [sum(256) | sumsq(256)]
__device__ float g_bnaff[512];                 // [scale(256) | shift(256)]
__device__ float g_c1[128];                    // b_on @ W1 + b1
__device__ float g_loss;

// ---------------- init ----------------
__global__ void k_zero() {
    int i = blockIdx.x * 256 + threadIdx.x;
    if (i < NN)  g_deg[i] = 0;
    if (i < 512) g_bnsum[i] = 0.f;
    if (i == 0)  g_loss = 0.f;
}
__global__ void k_hist(const int* __restrict__ row) {
    int e = blockIdx.x * 256 + threadIdx.x;
    if (e < EE) atomicAdd(&g_deg[row[e]], 1);
}

// ---------------- 3-pass scan ----------------
__global__ __launch_bounds__(1024) void k_scan1() {
    __shared__ int wsum[32];
    int t = threadIdx.x, lane = t & 31, wid = t >> 5;
    int idx = blockIdx.x * 1024 + t;
    int v = (idx < NN) ? g_deg[idx] : 0;
    int incl = v;
    #pragma unroll
    for (int s = 1; s < 32; s <<= 1) {
        int a = __shfl_up_sync(0xFFFFFFFFu, incl, s);
        if (lane >= s) incl += a;
    }
    if (lane == 31) wsum[wid] = incl;
    __syncthreads();
    if (wid == 0) {
        int wv = wsum[lane];
        #pragma unroll
        for (int s = 1; s < 32; s <<= 1) {
            int a = __shfl_up_sync(0xFFFFFFFFu, wv, s);
            if (lane >= s) wv += a;
        }
        wsum[lane] = wv;
    }
    __syncthreads();
    int excl = (wid > 0 ? wsum[wid - 1] : 0) + incl - v;
    if (idx < NN) g_off[idx] = excl;
    if (t == 0) g_btot[blockIdx.x] = wsum[31];
}
__global__ void k_scan2() {
    if (threadIdx.x == 0) {
        int run = 0;
        for (int i = 0; i < 49; i++) { int v = g_btot[i]; g_btot[i] = run; run += v; }
        g_off[NN] = run;
    }
}
__global__ __launch_bounds__(1024) void k_scan3() {
    int idx = blockIdx.x * 1024 + threadIdx.x;
    if (idx < NN) {
        int o = g_off[idx] + g_btot[blockIdx.x];
        g_off[idx] = o;
        g_cur[idx] = o;
    }
}
__global__ void k_scatter(const int* __restrict__ row, const int* __restrict__ col,
                          const float* __restrict__ w) {
    int e = blockIdx.x * 256 + threadIdx.x;
    if (e < EE) {
        int r = row[e];
        int p = atomicAdd(&g_cur[r], 1);
        g_scol[p] = col[e];
        g_sw[p]   = w[e];
    }
}

// ---------------- sparse aggregation of raw [x | perb] ----------------
__global__ __launch_bounds__(128) void k_aggregate(const float* __restrict__ x,
                                                   const float* __restrict__ perb) {
    int t = threadIdx.x, lane = t & 31, wid = t >> 5;
    int r = blockIdx.x * 2 + (wid >> 1);
    int part = wid & 1;
    const float4* src = part ? (const float4*)perb : (const float4*)x;
    int s = g_off[r], e = g_off[r + 1];
    float ax = 0.f, ay = 0.f, az = 0.f, aw = 0.f;
    int i = s;
    for (; i + 4 <= e; i += 4) {
        int c0 = g_scol[i], c1 = g_scol[i + 1], c2 = g_scol[i + 2], c3 = g_scol[i + 3];
        float w0 = g_sw[i], w1 = g_sw[i + 1], w2 = g_sw[i + 2], w3 = g_sw[i + 3];
        float4 h0 = src[(size_t)c0 * 32 + lane];
        float4 h1 = src[(size_t)c1 * 32 + lane];
        float4 h2 = src[(size_t)c2 * 32 + lane];
        float4 h3 = src[(size_t)c3 * 32 + lane];
        ax += w0 * h0.x + w1 * h1.x + w2 * h2.x + w3 * h3.x;
        ay += w0 * h0.y + w1 * h1.y + w2 * h2.y + w3 * h3.y;
        az += w0 * h0.z + w1 * h1.z + w2 * h2.z + w3 * h3.z;
        aw += w0 * h0.w + w1 * h1.w + w2 * h2.w + w3 * h3.w;
    }
    for (; i < e; i++) {
        int c = g_scol[i]; float w = g_sw[i];
        float4 h = src[(size_t)c * 32 + lane];
        ax += w * h.x; ay += w * h.y; az += w * h.z; aw += w * h.w;
    }
    ((float4*)g_AGGX)[(size_t)r * 64 + part * 32 + lane] = make_float4(ax, ay, az, aw);
}

// ---------------- bf16 hi/lo split wmma GEMM (128x128 tile, 256 thr) ----------------
typedef wmma::fragment<wmma::matrix_a, 16, 16, 16, __nv_bfloat16, wmma::row_major> FragA;
typedef wmma::fragment<wmma::matrix_b, 16, 16, 16, __nv_bfloat16, wmma::row_major> FragB;
typedef wmma::fragment<wmma::accumulator, 16, 16, 16, float> FragC;

#define BLD 136                         // bf16 image leading dim (elements)
#define SLD 132                         // fp32 scratch leading dim
#define SM_AH 0
#define SM_AL (128 * BLD)
#define SM_BH (2 * 128 * BLD)
#define SM_BL (3 * 128 * BLD)
#define DYN_SMEM (4 * 128 * BLD * 2)    // 139264 bytes

__device__ __forceinline__ void split_store(__nv_bfloat16* sm, int hioff, int looff,
                                            int pos, float v) {
    __nv_bfloat16 h = __float2bfloat16(v);
    sm[hioff + pos] = h;
    sm[looff + pos] = __float2bfloat16(v - __bfloat162float(h));
}
// stage W (128x128 row-major fp32) into bf16 hi/lo images
__device__ __forceinline__ void stage_B(__nv_bfloat16* sm, const float* __restrict__ W, int t) {
    #pragma unroll
    for (int i = 0; i < 64; i++) {
        int idx = t + i * 256;
        int r = idx >> 7, c = idx & 127;
        split_store(sm, SM_BH, SM_BL, r * BLD + c, W[idx]);
    }
}
// warp (wm=wid>>2 rows 64, wn=wid&3 cols 32) computes acc[4][2]
__device__ __forceinline__ void mm_block(const __nv_bfloat16* sm, FragC acc[4][2], int wid) {
    int wm = wid >> 2, wn = wid & 3;
    const __nv_bfloat16* AH = sm + SM_AH + wm * 64 * BLD;
    const __nv_bfloat16* AL = sm + SM_AL + wm * 64 * BLD;
    const __nv_bfloat16* BH = sm + SM_BH + wn * 32;
    const __nv_bfloat16* BL = sm + SM_BL + wn * 32;
    #pragma unroll
    for (int m = 0; m < 4; m++)
        #pragma unroll
        for (int ct = 0; ct < 2; ct++) wmma::fill_fragment(acc[m][ct], 0.f);
    #pragma unroll 1
    for (int ks = 0; ks < 8; ks++) {
        FragA ah[4], al[4];
        #pragma unroll
        for (int m = 0; m < 4; m++) {
            wmma::load_matrix_sync(ah[m], AH + m * 16 * BLD + ks * 16, BLD);
            wmma::load_matrix_sync(al[m], AL + m * 16 * BLD + ks * 16, BLD);
        }
        #pragma unroll
        for (int ct = 0; ct < 2; ct++) {
            FragB bh, bl;
            wmma::load_matrix_sync(bh, BH + ks * 16 * BLD + ct * 16, BLD);
            wmma::load_matrix_sync(bl, BL + ks * 16 * BLD + ct * 16, BLD);
            #pragma unroll
            for (int m = 0; m < 4; m++) {
                wmma::mma_sync(acc[m][ct], ah[m], bh, acc[m][ct]);
                wmma::mma_sync(acc[m][ct], ah[m], bl, acc[m][ct]);
                wmma::mma_sync(acc[m][ct], al[m], bh, acc[m][ct]);
            }
        }
    }
}

// ---------------- c1 = b_on @ W1 + b1 ----------------
__global__ void k_c1(const float* __restrict__ b_on, const float* __restrict__ W1,
                     const float* __restrict__ b1) {
    int n = threadIdx.x;
    float s = b1[n];
    for (int k = 0; k < 128; k++) s += b_on[k] * W1[k * 128 + n];
    g_c1[n] = s;
}

// ---------------- feature GEMMs: AGG[:,sec*128:+128] = AGGX_part @ W ----------------
__global__ __launch_bounds__(256, 1) void k_mm_feat(const float* __restrict__ W_on,
                                                    const float* __restrict__ W_tg) {
    extern __shared__ __nv_bfloat16 sm[];
    int t = threadIdx.x, wid = t >> 5;
    int sec = blockIdx.y, row0 = blockIdx.x * 128;
    stage_B(sm, (sec < 2) ? W_on : W_tg, t);
    const float* A = g_AGGX + (size_t)row0 * 256 + (sec & 1) * 128;
    #pragma unroll
    for (int i = 0; i < 64; i++) {
        int idx = t + i * 256;
        int r = idx >> 7, c = idx & 127;
        split_store(sm, SM_AH, SM_AL, r * BLD + c, A[(size_t)r * 256 + c]);
    }
    __syncthreads();
    FragC acc[4][2];
    mm_block(sm, acc, wid);
    int wm = wid >> 2, wn = wid & 3;
    float* Out = g_AGG + ((size_t)row0 + wm * 64) * 512 + sec * 128 + wn * 32;
    #pragma unroll
    for (int m = 0; m < 4; m++)
        #pragma unroll
        for (int ct = 0; ct < 2; ct++)
            wmma::store_matrix_sync(Out + (size_t)m * 16 * 512 + ct * 16, acc[m][ct], 512,
                                    wmma::mem_row_major);
}

// ---------------- embed = x + perb + agg_on_x + agg_on_p + b_on ----------------
__global__ void k_embed(const float* __restrict__ x, const float* __restrict__ perb,
                        const float* __restrict__ b_on, float* __restrict__ out) {
    int id = blockIdx.x * 256 + threadIdx.x;  // float4 index
    if (id < NN * 32) {
        int r = id >> 5, c = id & 31;
        float4 xv = ((const float4*)x)[id];
        float4 pv = ((const float4*)perb)[id];
        float4 a0 = ((const float4*)g_AGG)[(size_t)r * 128 + c];
        float4 a1 = ((const float4*)g_AGG)[(size_t)r * 128 + 32 + c];
        float4 bv = ((const float4*)b_on)[c];
        ((float4*)out)[id] = make_float4(xv.x + pv.x + a0.x + a1.x + bv.x,
                                         xv.y + pv.y + a0.y + a1.y + bv.y,
                                         xv.z + pv.z + a0.z + a1.z + bv.z,
                                         xv.w + pv.w + a0.w + a1.w + bv.w);
    }
}

// ---------------- pred stage 1: P1 = online @ W1 + c1 ; fused BN stats ----------------
__global__ __launch_bounds__(256, 1) void k_mm_p1(const float* __restrict__ W1) {
    extern __shared__ __nv_bfloat16 sm[];
    float* fs = (float*)sm;              // fp32 scratch overlays A images after mma
    int t = threadIdx.x, wid = t >> 5;
    int sec = blockIdx.y, row0 = blockIdx.x * 128;
    stage_B(sm, W1, t);
    #pragma unroll
    for (int i = 0; i < 64; i++) {
        int idx = t + i * 256;
        int r = idx >> 7, c = idx & 127;
        float v = g_AGG[((size_t)row0 + r) * 512 + c];
        if (sec) v += g_AGG[((size_t)row0 + r) * 512 + 128 + c];
        split_store(sm, SM_AH, SM_AL, r * BLD + c, v);
    }
    __syncthreads();
    FragC acc[4][2];
    mm_block(sm, acc, wid);
    __syncthreads();   // A images dead; fs reuse safe
    int wm = wid >> 2, wn = wid & 3;
    #pragma unroll
    for (int m = 0; m < 4; m++)
        #pragma unroll
        for (int ct = 0; ct < 2; ct++)
            wmma::store_matrix_sync(fs + (wm * 64 + m * 16) * SLD + wn * 32 + ct * 16,
                                    acc[m][ct], SLD, wmma::mem_row_major);
    __syncthreads();
    float* Out = g_P1 + (size_t)row0 * 256 + sec * 128;
    #pragma unroll
    for (int i = 0; i < 64; i++) {
        int idx = t + i * 256;
        int r = idx >> 7, c = idx & 127;
        float v = fs[r * SLD + c] + g_c1[c];
        Out[(size_t)r * 256 + c] = v;
        fs[r * SLD + c] = v;
    }
    __syncthreads();
    if (t < 128) {
        float s = 0.f, q = 0.f;
        int rmax = NN - row0; if (rmax > 128) rmax = 128;
        for (int r = 0; r < rmax; r++) {
            float v = fs[r * SLD + t];
            s += v; q += v * v;
        }
        atomicAdd(&g_bnsum[sec * 128 + t], s);
        atomicAdd(&g_bnsum[256 + sec * 128 + t], q);
    }
}

__global__ void k_bn_final(const float* __restrict__ bn_g, const float* __restrict__ bn_b) {
    int t = threadIdx.x;  // 0..255
    float inv_n = 1.f / (float)NN;
    float mean = g_bnsum[t] * inv_n;
    float var = g_bnsum[256 + t] * inv_n - mean * mean;
    int f = t & 127;
    float sc = bn_g[f] * rsqrtf(var + 1e-5f);
    g_bnaff[t] = sc;
    g_bnaff[256 + t] = bn_b[f] - mean * sc;
}

// ---------------- pred stage 2 + cosine loss (P2 never leaves the block) ----------------
__global__ __launch_bounds__(256, 1) void k_mm_p2(const float* __restrict__ b_tg,
                                                  const float* __restrict__ prelu_a,
                                                  const float* __restrict__ W2,
                                                  const float* __restrict__ b2) {
    extern __shared__ __nv_bfloat16 sm[];
    float* fs = (float*)sm;
    __shared__ float warp_l[8];
    int t = threadIdx.x, wid = t >> 5, lane = t & 31;
    int sec = blockIdx.y, row0 = blockIdx.x * 128;
    float alpha = prelu_a[0];
    stage_B(sm, W2, t);
    #pragma unroll
    for (int i = 0; i < 64; i++) {
        int idx = t + i * 256;
        int r = idx >> 7, c = idx & 127;
        float v = g_P1[((size_t)row0 + r) * 256 + sec * 128 + c] * g_bnaff[sec * 128 + c]
                  + g_bnaff[256 + sec * 128 + c];
        v = v > 0.f ? v : alpha * v;
        split_store(sm, SM_AH, SM_AL, r * BLD + c, v);
    }
    __syncthreads();
    FragC acc[4][2];
    mm_block(sm, acc, wid);
    __syncthreads();
    int wm = wid >> 2, wn = wid & 3;
    #pragma unroll
    for (int m = 0; m < 4; m++)
        #pragma unroll
        for (int ct = 0; ct < 2; ct++)
            wmma::store_matrix_sync(fs + (wm * 64 + m * 16) * SLD + wn * 32 + ct * 16,
                                    acc[m][ct], SLD, wmma::mem_row_major);
    __syncthreads();

    float4 bb = *(const float4*)(b2 + lane * 4);
    float4 bt = *(const float4*)(b_tg + lane * 4);
    float lsum = 0.f;
    for (int rr = 0; rr < 16; rr++) {
        int r = wid * 16 + rr;
        int gr = row0 + r;
        if (gr < NN) {
            float p0 = fs[r * SLD + lane * 4]     + bb.x;
            float p1 = fs[r * SLD + lane * 4 + 1] + bb.y;
            float p2 = fs[r * SLD + lane * 4 + 2] + bb.z;
            float p3 = fs[r * SLD + lane * 4 + 3] + bb.w;
            float4 tg = *(const float4*)(g_AGG + (size_t)gr * 512 + 256 + lane * 4);
            if (sec == 0) {  // target_x = agg_tg_x + agg_tg_p + b_tg
                float4 u = *(const float4*)(g_AGG + (size_t)gr * 512 + 384 + lane * 4);
                tg.x += u.x; tg.y += u.y; tg.z += u.z; tg.w += u.w;
            }
            tg.x += bt.x; tg.y += bt.y; tg.z += bt.z; tg.w += bt.w;
            float dot = p0 * tg.x + p1 * tg.y + p2 * tg.z + p3 * tg.w;
            float np  = p0 * p0 + p1 * p1 + p2 * p2 + p3 * p3;
            float nt  = tg.x * tg.x + tg.y * tg.y + tg.z * tg.z + tg.w * tg.w;
            #pragma unroll
            for (int s = 16; s; s >>= 1) {
                dot += __shfl_xor_sync(0xFFFFFFFFu, dot, s);
                np  += __shfl_xor_sync(0xFFFFFFFFu, np, s);
                nt  += __shfl_xor_sync(0xFFFFFFFFu, nt, s);
            }
            if (lane == 0) {
                float d1 = fmaxf(sqrtf(np), 1e-12f);
                float d2 = fmaxf(sqrtf(nt), 1e-12f);
                lsum += 2.f - 2.f * dot / (d1 * d2);
            }
        }
    }
    if (lane == 0) warp_l[wid] = lsum;
    __syncthreads();
    if (t == 0) {
        float s = 0.f;
        #pragma unroll
        for (int w = 0; w < 8; w++) s += warp_l[w];
        atomicAdd(&g_loss, s);
    }
}

__global__ void k_final(float* out, int out_size) {
    out[out_size - 1] = g_loss * (1.f / (float)NN);
}

// ---------------- host ----------------
extern "C" void kernel_launch(void* const* d_in, const int* in_sizes, int n_in,
                              void* d_out, int out_size) {
    const float* x       = (const float*)d_in[0];
    const float* perb    = (const float*)d_in[1];
    const int*   erow    = (const int*)d_in[2];
    const int*   ecol    = (const int*)d_in[3];
    const float* ew      = (const float*)d_in[4];
    const float* W_on    = (const float*)d_in[5];
    const float* b_on    = (const float*)d_in[6];
    const float* W_tg    = (const float*)d_in[7];
    const float* b_tg    = (const float*)d_in[8];
    const float* W1      = (const float*)d_in[9];
    const float* b1      = (const float*)d_in[10];
    const float* bn_g    = (const float*)d_in[11];
    const float* bn_b    = (const float*)d_in[12];
    const float* prelu_a = (const float*)d_in[13];
    const float* W2      = (const float*)d_in[14];
    const float* b2      = (const float*)d_in[15];
    float* out = (float*)d_out;

    cudaFuncSetAttribute(k_mm_feat, cudaFuncAttributeMaxDynamicSharedMemorySize, DYN_SMEM);
    cudaFuncSetAttribute(k_mm_p1,   cudaFuncAttributeMaxDynamicSharedMemorySize, DYN_SMEM);
    cudaFuncSetAttribute(k_mm_p2,   cudaFuncAttributeMaxDynamicSharedMemorySize, DYN_SMEM);

    k_zero<<<196, 256>>>();
    k_hist<<<3125, 256>>>(erow);
    k_c1<<<1, 128>>>(b_on, W1, b1);
    k_scan1<<<49, 1024>>>();
    k_scan2<<<1, 32>>>();
    k_scan3<<<49, 1024>>>();
    k_scatter<<<3125, 256>>>(erow, ecol, ew);
    k_aggregate<<<25000, 128>>>(x, perb);
    k_mm_feat<<<dim3(391, 4), 256, DYN_SMEM>>>(W_on, W_tg);
    k_embed<<<6250, 256>>>(x, perb, b_on, out);
    k_mm_p1<<<dim3(391, 2), 256, DYN_SMEM>>>(W1);
    k_bn_final<<<1, 256>>>(bn_g, bn_b);
    k_mm_p2<<<dim3(391, 2), 256, DYN_SMEM>>>(b_tg, prelu_a, W2, b2);
    k_final<<<1, 1>>>(out, out_size);
}

// round 11
// speedup vs baseline: 2.5749x; 1.1457x over previous
#include <cuda_runtime.h>
#include <cuda_bf16.h>
#include <mma.h>
#include <math.h>
#include <cstdint>

using namespace nvcuda;

#define NN    50000
#define NPAD  50048          // 391 * 128
#define EE    800000

// ---------------- scratch (device globals; no allocation) ----------------
__device__ float g_AGGX[(size_t)NPAD * 256];   // aggregated [x | perb]
__device__ float g_AGG[(size_t)NPAD * 512];    // [on_x | on_p | tg_x | tg_p]
__device__ float g_P1[(size_t)NPAD * 256];     // [h1x | h1y]
__device__ int   g_deg[NN];
__device__ int   g_off[NN + 8];
__device__ int   g_cur[NN];
__device__ int   g_btot[64];
__device__ int   g_scol[EE];
__device__ float g_sw[EE];
__device__ float g_bnsum[512];                 // [sum(256) | sumsq(256)]
__device__ float g_bnaff[512];                 // [scale(256) | shift(256)]
__device__ float g_c1[128];                    // b_on @ W1 + b1
__device__ float g_loss;

// ---------------- init ----------------
__global__ void k_zero() {
    int i = blockIdx.x * 256 + threadIdx.x;
    if (i < NN)  g_deg[i] = 0;
    if (i < 512) g_bnsum[i] = 0.f;
    if (i == 0)  g_loss = 0.f;
}
__global__ void k_hist(const int* __restrict__ row) {
    int e = blockIdx.x * 256 + threadIdx.x;
    if (e < EE) atomicAdd(&g_deg[row[e]], 1);
}

// ---------------- 3-pass scan ----------------
__global__ __launch_bounds__(1024) void k_scan1() {
    __shared__ int wsum[32];
    int t = threadIdx.x, lane = t & 31, wid = t >> 5;
    int idx = blockIdx.x * 1024 + t;
    int v = (idx < NN) ? g_deg[idx] : 0;
    int incl = v;
    #pragma unroll
    for (int s = 1; s < 32; s <<= 1) {
        int a = __shfl_up_sync(0xFFFFFFFFu, incl, s);
        if (lane >= s) incl += a;
    }
    if (lane == 31) wsum[wid] = incl;
    __syncthreads();
    if (wid == 0) {
        int wv = wsum[lane];
        #pragma unroll
        for (int s = 1; s < 32; s <<= 1) {
            int a = __shfl_up_sync(0xFFFFFFFFu, wv, s);
            if (lane >= s) wv += a;
        }
        wsum[lane] = wv;
    }
    __syncthreads();
    int excl = (wid > 0 ? wsum[wid - 1] : 0) + incl - v;
    if (idx < NN) g_off[idx] = excl;
    if (t == 0) g_btot[blockIdx.x] = wsum[31];
}
__global__ void k_scan2() {
    if (threadIdx.x == 0) {
        int run = 0;
        for (int i = 0; i < 49; i++) { int v = g_btot[i]; g_btot[i] = run; run += v; }
        g_off[NN] = run;
    }
}
__global__ __launch_bounds__(1024) void k_scan3() {
    int idx = blockIdx.x * 1024 + threadIdx.x;
    if (idx < NN) {
        int o = g_off[idx] + g_btot[blockIdx.x];
        g_off[idx] = o;
        g_cur[idx] = o;
    }
}
__global__ void k_scatter(const int* __restrict__ row, const int* __restrict__ col,
                          const float* __restrict__ w) {
    int e = blockIdx.x * 256 + threadIdx.x;
    if (e < EE) {
        int r = row[e];
        int p = atomicAdd(&g_cur[r], 1);
        g_scol[p] = col[e];
        g_sw[p]   = w[e];
    }
}

// ---------------- sparse aggregation of raw [x | perb] ----------------
__global__ __launch_bounds__(128) void k_aggregate(const float* __restrict__ x,
                                                   const float* __restrict__ perb) {
    int t = threadIdx.x, lane = t & 31, wid = t >> 5;
    int r = blockIdx.x * 2 + (wid >> 1);
    int part = wid & 1;
    const float4* src = part ? (const float4*)perb : (const float4*)x;
    int s = g_off[r], e = g_off[r + 1];
    float ax = 0.f, ay = 0.f, az = 0.f, aw = 0.f;
    int i = s;
    for (; i + 4 <= e; i += 4) {
        int c0 = g_scol[i], c1 = g_scol[i + 1], c2 = g_scol[i + 2], c3 = g_scol[i + 3];
        float w0 = g_sw[i], w1 = g_sw[i + 1], w2 = g_sw[i + 2], w3 = g_sw[i + 3];
        float4 h0 = src[(size_t)c0 * 32 + lane];
        float4 h1 = src[(size_t)c1 * 32 + lane];
        float4 h2 = src[(size_t)c2 * 32 + lane];
        float4 h3 = src[(size_t)c3 * 32 + lane];
        ax += w0 * h0.x + w1 * h1.x + w2 * h2.x + w3 * h3.x;
        ay += w0 * h0.y + w1 * h1.y + w2 * h2.y + w3 * h3.y;
        az += w0 * h0.z + w1 * h1.z + w2 * h2.z + w3 * h3.z;
        aw += w0 * h0.w + w1 * h1.w + w2 * h2.w + w3 * h3.w;
    }
    for (; i < e; i++) {
        int c = g_scol[i]; float w = g_sw[i];
        float4 h = src[(size_t)c * 32 + lane];
        ax += w * h.x; ay += w * h.y; az += w * h.z; aw += w * h.w;
    }
    ((float4*)g_AGGX)[(size_t)r * 64 + part * 32 + lane] = make_float4(ax, ay, az, aw);
}

// ---------------- bf16 hi/lo split wmma GEMM (128x128 tile, 512 thr, 16 warps) ----------------
typedef wmma::fragment<wmma::matrix_a, 16, 16, 16, __nv_bfloat16, wmma::row_major> FragA;
typedef wmma::fragment<wmma::matrix_b, 16, 16, 16, __nv_bfloat16, wmma::row_major> FragB;
typedef wmma::fragment<wmma::accumulator, 16, 16, 16, float> FragC;

#define BLD 136                         // bf16 image leading dim (elements)
#define SLD 132                         // fp32 scratch leading dim
#define TILE (128 * BLD)                // elements per image (17408)
#define SM_AXH 0
#define SM_AXL (1 * TILE)
#define SM_AYH (2 * TILE)
#define SM_AYL (3 * TILE)
#define SM_BH  (4 * TILE)
#define SM_BL  (5 * TILE)
#define DYN_SMEM (6 * TILE * 2)         // 208896 bytes

__device__ __forceinline__ void split_store(__nv_bfloat16* sm, int hioff, int looff,
                                            int pos, float v) {
    __nv_bfloat16 h = __float2bfloat16(v);
    sm[hioff + pos] = h;
    sm[looff + pos] = __float2bfloat16(v - __bfloat162float(h));
}
// stage W (128x128 row-major fp32) into bf16 hi/lo B images (512 thr)
__device__ __forceinline__ void stage_B(__nv_bfloat16* sm, const float* __restrict__ W, int t) {
    #pragma unroll
    for (int i = 0; i < 32; i++) {
        int idx = t + i * 512;
        int r = idx >> 7, c = idx & 127;
        split_store(sm, SM_BH, SM_BL, r * BLD + c, W[idx]);
    }
}
// 16 warps: wm=wid>>2 rows wm*32..+31, wn=wid&3 cols wn*32..+31; acc[2][2]
__device__ __forceinline__ void mm_block(const __nv_bfloat16* sm, int a_hi, FragC acc[2][2],
                                         int wid) {
    int wm = wid >> 2, wn = wid & 3;
    const __nv_bfloat16* AH = sm + a_hi + wm * 32 * BLD;
    const __nv_bfloat16* AL = AH + TILE;
    const __nv_bfloat16* BH = sm + SM_BH + wn * 32;
    const __nv_bfloat16* BL = sm + SM_BL + wn * 32;
    #pragma unroll
    for (int m = 0; m < 2; m++)
        #pragma unroll
        for (int ct = 0; ct < 2; ct++) wmma::fill_fragment(acc[m][ct], 0.f);
    #pragma unroll 1
    for (int ks = 0; ks < 8; ks++) {
        FragA ah[2], al[2];
        #pragma unroll
        for (int m = 0; m < 2; m++) {
            wmma::load_matrix_sync(ah[m], AH + m * 16 * BLD + ks * 16, BLD);
            wmma::load_matrix_sync(al[m], AL + m * 16 * BLD + ks * 16, BLD);
        }
        #pragma unroll
        for (int ct = 0; ct < 2; ct++) {
            FragB bh, bl;
            wmma::load_matrix_sync(bh, BH + ks * 16 * BLD + ct * 16, BLD);
            wmma::load_matrix_sync(bl, BL + ks * 16 * BLD + ct * 16, BLD);
            #pragma unroll
            for (int m = 0; m < 2; m++) {
                wmma::mma_sync(acc[m][ct], ah[m], bh, acc[m][ct]);
                wmma::mma_sync(acc[m][ct], ah[m], bl, acc[m][ct]);
                wmma::mma_sync(acc[m][ct], al[m], bh, acc[m][ct]);
            }
        }
    }
}
// store product to global (ld 512) at column base seccol
__device__ __forceinline__ void store_prod_g(FragC acc[2][2], float* outb, int wid) {
    int wm = wid >> 2, wn = wid & 3;
    #pragma unroll
    for (int m = 0; m < 2; m++)
        #pragma unroll
        for (int ct = 0; ct < 2; ct++)
            wmma::store_matrix_sync(outb + (size_t)(wm * 32 + m * 16) * 512 + wn * 32 + ct * 16,
                                    acc[m][ct], 512, wmma::mem_row_major);
}
// store product to fp32 smem scratch (ld SLD)
__device__ __forceinline__ void store_prod_s(FragC acc[2][2], float* fs, int wid) {
    int wm = wid >> 2, wn = wid & 3;
    #pragma unroll
    for (int m = 0; m < 2; m++)
        #pragma unroll
        for (int ct = 0; ct < 2; ct++)
            wmma::store_matrix_sync(fs + (wm * 32 + m * 16) * SLD + wn * 32 + ct * 16,
                                    acc[m][ct], SLD, wmma::mem_row_major);
}

// ---------------- c1 = b_on @ W1 + b1 ----------------
__global__ void k_c1(const float* __restrict__ b_on, const float* __restrict__ W1,
                     const float* __restrict__ b1) {
    int n = threadIdx.x;
    float s = b1[n];
    for (int k = 0; k < 128; k++) s += b_on[k] * W1[k * 128 + n];
    g_c1[n] = s;
}

// ---------------- feature GEMMs (all 4 products) + fused embed ----------------
__global__ __launch_bounds__(512, 1) void k_mm_feat(const float* __restrict__ x,
                                                    const float* __restrict__ perb,
                                                    const float* __restrict__ b_on,
                                                    const float* __restrict__ W_on,
                                                    const float* __restrict__ W_tg,
                                                    float* __restrict__ out) {
    extern __shared__ __nv_bfloat16 sm[];
    int t = threadIdx.x, wid = t >> 5;
    int row0 = blockIdx.x * 128;
    // stage A: x part -> AX images, perb part -> AY images
    #pragma unroll
    for (int i = 0; i < 32; i++) {
        int idx = t + i * 512;
        int r = idx >> 7, c = idx & 127;
        int gr = row0 + r;
        float vx = 0.f, vp = 0.f;
        if (gr < NN) {
            vx = g_AGGX[(size_t)gr * 256 + c];
            vp = g_AGGX[(size_t)gr * 256 + 128 + c];
        }
        split_store(sm, SM_AXH, SM_AXL, r * BLD + c, vx);
        split_store(sm, SM_AYH, SM_AYL, r * BLD + c, vp);
    }
    stage_B(sm, W_on, t);
    __syncthreads();

    FragC acc[2][2];
    float* aggb = g_AGG + (size_t)row0 * 512;
    mm_block(sm, SM_AXH, acc, wid);            // on_x
    store_prod_g(acc, aggb, wid);
    mm_block(sm, SM_AYH, acc, wid);            // on_p
    store_prod_g(acc, aggb + 128, wid);
    __syncthreads();                            // global stores visible block-wide

    // fused embed = x + perb + on_x + on_p + b_on
    #pragma unroll
    for (int i = 0; i < 8; i++) {
        int idx = t + i * 512;                  // float4 idx within tile
        int r = idx >> 5, c4 = idx & 31;
        int gr = row0 + r;
        if (gr < NN) {
            float4 xv = ((const float4*)x)[(size_t)gr * 32 + c4];
            float4 pv = ((const float4*)perb)[(size_t)gr * 32 + c4];
            float4 a0 = ((const float4*)g_AGG)[(size_t)gr * 128 + c4];
            float4 a1 = ((const float4*)g_AGG)[(size_t)gr * 128 + 32 + c4];
            float4 bv = ((const float4*)b_on)[c4];
            ((float4*)out)[(size_t)gr * 32 + c4] =
                make_float4(xv.x + pv.x + a0.x + a1.x + bv.x,
                            xv.y + pv.y + a0.y + a1.y + bv.y,
                            xv.z + pv.z + a0.z + a1.z + bv.z,
                            xv.w + pv.w + a0.w + a1.w + bv.w);
        }
    }
    // restage B with W_tg
    stage_B(sm, W_tg, t);
    __syncthreads();
    mm_block(sm, SM_AXH, acc, wid);            // tg_x
    store_prod_g(acc, aggb + 256, wid);
    mm_block(sm, SM_AYH, acc, wid);            // tg_p
    store_prod_g(acc, aggb + 384, wid);
}

// ---------------- pred stage 1 (both secs): P1 = online @ W1 + c1 ; fused BN stats ----------------
__global__ __launch_bounds__(512, 1) void k_mm_p1(const float* __restrict__ W1) {
    extern __shared__ __nv_bfloat16 sm[];
    float* fs0 = (float*)sm;                              // overlays AX images
    float* fs1 = (float*)((char*)sm + SM_AYH * 2);        // overlays AY images
    int t = threadIdx.x, wid = t >> 5;
    int row0 = blockIdx.x * 128;
    #pragma unroll
    for (int i = 0; i < 32; i++) {
        int idx = t + i * 512;
        int r = idx >> 7, c = idx & 127;
        int gr = row0 + r;
        float v1 = 0.f, v2 = 0.f;
        if (gr < NN) {
            v1 = g_AGG[(size_t)gr * 512 + c];
            v2 = v1 + g_AGG[(size_t)gr * 512 + 128 + c];
        }
        split_store(sm, SM_AXH, SM_AXL, r * BLD + c, v1);
        split_store(sm, SM_AYH, SM_AYL, r * BLD + c, v2);
    }
    stage_B(sm, W1, t);
    __syncthreads();
    FragC acc[2][2];
    mm_block(sm, SM_AXH, acc, wid);            // sec 0 (online_x)
    __syncthreads();                            // AX images dead
    store_prod_s(acc, fs0, wid);
    mm_block(sm, SM_AYH, acc, wid);            // sec 1 (online_y)
    __syncthreads();                            // AY images dead
    store_prod_s(acc, fs1, wid);
    __syncthreads();
    // write P1 (+c1) and keep in scratch for BN stats
    #pragma unroll
    for (int i = 0; i < 64; i++) {
        int idx = t + i * 512;                 // 0..32767
        int sec = idx >> 14, rem = idx & 16383;
        int r = rem >> 7, c = rem & 127;
        float* fs = sec ? fs1 : fs0;
        float v = fs[r * SLD + c] + g_c1[c];
        fs[r * SLD + c] = v;
        g_P1[((size_t)row0 + r) * 256 + sec * 128 + c] = v;
    }
    __syncthreads();
    if (t < 256) {
        int sec = t >> 7, col = t & 127;
        const float* fs = sec ? fs1 : fs0;
        float s = 0.f, q = 0.f;
        int rmax = NN - row0; if (rmax > 128) rmax = 128;
        for (int r = 0; r < rmax; r++) {
            float v = fs[r * SLD + col];
            s += v; q += v * v;
        }
        atomicAdd(&g_bnsum[sec * 128 + col], s);
        atomicAdd(&g_bnsum[256 + sec * 128 + col], q);
    }
}

__global__ void k_bn_final(const float* __restrict__ bn_g, const float* __restrict__ bn_b) {
    int t = threadIdx.x;  // 0..255
    float inv_n = 1.f / (float)NN;
    float mean = g_bnsum[t] * inv_n;
    float var = g_bnsum[256 + t] * inv_n - mean * mean;
    int f = t & 127;
    float sc = bn_g[f] * rsqrtf(var + 1e-5f);
    g_bnaff[t] = sc;
    g_bnaff[256 + t] = bn_b[f] - mean * sc;
}

// ---------------- pred stage 2 (both secs) + cosine loss ----------------
__global__ __launch_bounds__(512, 1) void k_mm_p2(const float* __restrict__ b_tg,
                                                  const float* __restrict__ prelu_a,
                                                  const float* __restrict__ W2,
                                                  const float* __restrict__ b2) {
    extern __shared__ __nv_bfloat16 sm[];
    float* fs0 = (float*)sm;
    float* fs1 = (float*)((char*)sm + SM_AYH * 2);
    __shared__ float warp_l[16];
    int t = threadIdx.x, wid = t >> 5, lane = t & 31;
    int row0 = blockIdx.x * 128;
    float alpha = prelu_a[0];
    #pragma unroll
    for (int i = 0; i < 32; i++) {
        int idx = t + i * 512;
        int r = idx >> 7, c = idx & 127;
        int gr = row0 + r;
        float vx = 0.f, vy = 0.f;
        if (gr < NN) {
            float hx = g_P1[(size_t)gr * 256 + c];
            float hy = g_P1[(size_t)gr * 256 + 128 + c];
            vx = hx * g_bnaff[c] + g_bnaff[256 + c];
            vy = hy * g_bnaff[128 + c] + g_bnaff[384 + c];
            vx = vx > 0.f ? vx : alpha * vx;
            vy = vy > 0.f ? vy : alpha * vy;
        }
        split_store(sm, SM_AXH, SM_AXL, r * BLD + c, vx);
        split_store(sm, SM_AYH, SM_AYL, r * BLD + c, vy);
    }
    stage_B(sm, W2, t);
    __syncthreads();
    FragC acc[2][2];
    mm_block(sm, SM_AXH, acc, wid);            // px
    __syncthreads();
    store_prod_s(acc, fs0, wid);
    mm_block(sm, SM_AYH, acc, wid);            // py
    __syncthreads();
    store_prod_s(acc, fs1, wid);
    __syncthreads();

    float4 bb = *(const float4*)(b2 + lane * 4);
    float4 bt = *(const float4*)(b_tg + lane * 4);
    float lsum = 0.f;
    for (int j = 0; j < 16; j++) {
        int job = wid * 16 + j;                // 0..255
        int sec = job >> 7, r = job & 127;
        int gr = row0 + r;
        if (gr < NN) {
            const float* fs = sec ? fs1 : fs0;
            float p0 = fs[r * SLD + lane * 4]     + bb.x;
            float p1 = fs[r * SLD + lane * 4 + 1] + bb.y;
            float p2 = fs[r * SLD + lane * 4 + 2] + bb.z;
            float p3 = fs[r * SLD + lane * 4 + 3] + bb.w;
            float4 tg = *(const float4*)(g_AGG + (size_t)gr * 512 + 256 + lane * 4);
            if (sec == 0) {  // target_x = tg_x + tg_p + b_tg
                float4 u = *(const float4*)(g_AGG + (size_t)gr * 512 + 384 + lane * 4);
                tg.x += u.x; tg.y += u.y; tg.z += u.z; tg.w += u.w;
            }
            tg.x += bt.x; tg.y += bt.y; tg.z += bt.z; tg.w += bt.w;
            float dot = p0 * tg.x + p1 * tg.y + p2 * tg.z + p3 * tg.w;
            float np  = p0 * p0 + p1 * p1 + p2 * p2 + p3 * p3;
            float nt  = tg.x * tg.x + tg.y * tg.y + tg.z * tg.z + tg.w * tg.w;
            #pragma unroll
            for (int s = 16; s; s >>= 1) {
                dot += __shfl_xor_sync(0xFFFFFFFFu, dot, s);
                np  += __shfl_xor_sync(0xFFFFFFFFu, np, s);
                nt  += __shfl_xor_sync(0xFFFFFFFFu, nt, s);
            }
            if (lane == 0) {
                float d1 = fmaxf(sqrtf(np), 1e-12f);
                float d2 = fmaxf(sqrtf(nt), 1e-12f);
                lsum += 2.f - 2.f * dot / (d1 * d2);
            }
        }
    }
    if (lane == 0) warp_l[wid] = lsum;
    __syncthreads();
    if (t == 0) {
        float s = 0.f;
        #pragma unroll
        for (int w = 0; w < 16; w++) s += warp_l[w];
        atomicAdd(&g_loss, s);
    }
}

__global__ void k_final(float* out, int out_size) {
    out[out_size - 1] = g_loss * (1.f / (float)NN);
}

// ---------------- host ----------------
extern "C" void kernel_launch(void* const* d_in, const int* in_sizes, int n_in,
                              void* d_out, int out_size) {
    const float* x       = (const float*)d_in[0];
    const float* perb    = (const float*)d_in[1];
    const int*   erow    = (const int*)d_in[2];
    const int*   ecol    = (const int*)d_in[3];
    const float* ew      = (const float*)d_in[4];
    const float* W_on    = (const float*)d_in[5];
    const float* b_on    = (const float*)d_in[6];
    const float* W_tg    = (const float*)d_in[7];
    const float* b_tg    = (const float*)d_in[8];
    const float* W1      = (const float*)d_in[9];
    const float* b1      = (const float*)d_in[10];
    const float* bn_g    = (const float*)d_in[11];
    const float* bn_b    = (const float*)d_in[12];
    const float* prelu_a = (const float*)d_in[13];
    const float* W2      = (const float*)d_in[14];
    const float* b2      = (const float*)d_in[15];
    float* out = (float*)d_out;

    cudaFuncSetAttribute(k_mm_feat, cudaFuncAttributeMaxDynamicSharedMemorySize, DYN_SMEM);
    cudaFuncSetAttribute(k_mm_p1,   cudaFuncAttributeMaxDynamicSharedMemorySize, DYN_SMEM);
    cudaFuncSetAttribute(k_mm_p2,   cudaFuncAttributeMaxDynamicSharedMemorySize, DYN_SMEM);

    k_zero<<<196, 256>>>();
    k_hist<<<3125, 256>>>(erow);
    k_c1<<<1, 128>>>(b_on, W1, b1);
    k_scan1<<<49, 1024>>>();
    k_scan2<<<1, 32>>>();
    k_scan3<<<49, 1024>>>();
    k_scatter<<<3125, 256>>>(erow, ecol, ew);
    k_aggregate<<<25000, 128>>>(x, perb);
    k_mm_feat<<<391, 512, DYN_SMEM>>>(x, perb, b_on, W_on, W_tg, out);
    k_mm_p1<<<391, 512, DYN_SMEM>>>(W1);
    k_bn_final<<<1, 256>>>(bn_g, bn_b);
    k_mm_p2<<<391, 512, DYN_SMEM>>>(b_tg, prelu_a, W2, b2);
    k_final<<<1, 1>>>(out, out_size);
}